// round 4
// baseline (speedup 1.0000x reference)
#include <cuda_runtime.h>
#include <cstdint>

#define D_LEN 32768
typedef unsigned long long u64;

// ---------------- scratch (static device globals, no allocation) ------------
__device__ __align__(256) float g_a[64 * D_LEN];
__device__ __align__(256) float g_s[64 * D_LEN];
__device__ __align__(256) float g_c[64 * D_LEN];
__device__ double g_part[1280];

__constant__ int c_PI[10] = {0,0,0,0,1,1,1,2,2,3};
__constant__ int c_PJ[10] = {0,1,2,3,1,2,3,2,3,3};

// ---------------- fast fp32 sincos(x), |x| <~ 1000 --------------------------
__device__ __forceinline__ void sincos_fast(float x, float& s_out, float& c_out) {
    const float PIO2_A = 1.5707963705062866f;      // RN(pi/2)
    const float PIO2_B = -4.3711388286737929e-8f;  // pi/2 - PIO2_A
    float q = rintf(x * 0.63661977236758134f);     // 2/pi
    int qi = (int)q;
    float r = fmaf(q, -PIO2_A, x);
    r = fmaf(q, -PIO2_B, r);
    float z = r * r;
    float ps = fmaf(z, fmaf(z, -1.9515295891e-4f, 8.3321608736e-3f), -1.6666654611e-1f);
    float sinr = fmaf(r * z, ps, r);
    float pc = fmaf(z, fmaf(z, 2.443315711809948e-5f, -1.388731625493765e-3f),
                    4.166664568298827e-2f);
    float cosr = fmaf(z * z, pc, fmaf(z, -0.5f, 1.0f));
    float s, c;
    if (qi & 1) { s = cosr; c = -sinr; } else { s = sinr; c = cosr; }
    if (qi & 2) { s = -s; c = -c; }
    s_out = s; c_out = c;
}

// ---------------- pool(4) + sincos(100*m), 4 outputs/thread -----------------
__global__ void pool_kernel(const float* __restrict__ A, const float* __restrict__ B) {
    int idx = blockIdx.x * blockDim.x + threadIdx.x;   // [0, 524288)
    int tensor = idx >> 18;
    int rem = idx & 262143;
    int b  = rem >> 13;                                // 0..31
    int fg = rem & 8191;                               // feat group (4 feats)
    int c   = fg >> 6;
    int ph  = (fg >> 2) & 15;
    int pw0 = (fg & 3) * 4;
    const float* src = tensor ? B : A;
    const float* p = src + ((((b * 128 + c) * 64) + ph * 4) * 64 + pw0 * 4);

    float s0 = 0.f, s1 = 0.f, s2 = 0.f, s3 = 0.f;
    #pragma unroll
    for (int r = 0; r < 4; ++r) {
        const float* q = p + r * 64;
        float4 v0 = __ldcs((const float4*)(q));
        float4 v1 = __ldcs((const float4*)(q + 4));
        float4 v2 = __ldcs((const float4*)(q + 8));
        float4 v3 = __ldcs((const float4*)(q + 12));
        s0 += (v0.x + v0.y) + (v0.z + v0.w);
        s1 += (v1.x + v1.y) + (v1.z + v1.w);
        s2 += (v2.x + v2.y) + (v2.z + v2.w);
        s3 += (v3.x + v3.y) + (v3.z + v3.w);
    }
    float4 m = make_float4(s0 * 0.0625f, s1 * 0.0625f, s2 * 0.0625f, s3 * 0.0625f);
    float4 sv, cv;
    sincos_fast(100.0f * m.x, sv.x, cv.x);
    sincos_fast(100.0f * m.y, sv.y, cv.y);
    sincos_fast(100.0f * m.z, sv.z, cv.z);
    sincos_fast(100.0f * m.w, sv.w, cv.w);

    int row = tensor * 32 + b;
    int off = row * D_LEN + fg * 4;
    *(float4*)(g_a + off) = m;
    *(float4*)(g_s + off) = sv;
    *(float4*)(g_c + off) = cv;
}

// ---------------- pair kernel ------------------------------------------------
__device__ __forceinline__ void cp16(uint32_t dst, const float* src) {
    asm volatile("cp.async.cg.shared.global [%0], [%1], 16;\n" :: "r"(dst), "l"(src));
}
__device__ __forceinline__ float frcp(float x) {
    float r; asm("rcp.approx.ftz.f32 %0, %1;" : "=f"(r) : "f"(x)); return r;
}
__device__ __forceinline__ u64 fma2_(u64 a, u64 b, u64 c) {
    u64 r; asm("fma.rn.f32x2 %0, %1, %2, %3;" : "=l"(r) : "l"(a), "l"(b), "l"(c)); return r;
}
__device__ __forceinline__ u64 mul2_(u64 a, u64 b) {
    u64 r; asm("mul.rn.f32x2 %0, %1, %2;" : "=l"(r) : "l"(a), "l"(b)); return r;
}
__device__ __forceinline__ float f2lo(u64 v) { return __uint_as_float((unsigned)v); }
__device__ __forceinline__ float f2hi(u64 v) { return __uint_as_float((unsigned)(v >> 32)); }

#define M1X2  0xBF800000BF800000ULL   /* (-1.0f, -1.0f) */
#define EPSX2 0x3300000033000000ULL   /* (2^-25, 2^-25) */

// 2 terms (adjacent k) fully packed. term = (su*cv - cu*sv) / (d + sign(d)*eps)
// On exact collision d==0: numerator is EXACTLY 0 (both products round
// identically), denominator = eps -> contribution 0 (true 100; ~1e-7 of budget).
__device__ __forceinline__ void term2(u64 au, u64 su, u64 cu,
                                      u64 av, u64 sv, u64 cv, u64& acc) {
    u64 d   = fma2_(av, M1X2, au);                                      // au - av
    u64 sgn = (d & 0x8000000080000000ULL) | 0x3F8000003F800000ULL;      // +-1.0f
    u64 den = fma2_(sgn, EPSX2, d);                                     // d + sgn*eps
    float w0 = frcp(f2lo(den));
    float w1 = frcp(f2hi(den));
    u64 w = ((u64)__float_as_uint(w1) << 32) | (u64)__float_as_uint(w0);
    u64 p1 = mul2_(su, cv);
    u64 t2 = mul2_(cu, sv);
    u64 n  = fma2_(t2, M1X2, p1);                                       // p1 - t2
    acc = fma2_(n, w, acc);
}

__device__ __forceinline__ void term4(const ulonglong2& au, const ulonglong2& su,
                                      const ulonglong2& cu, const ulonglong2& av,
                                      const ulonglong2& sv, const ulonglong2& cv,
                                      u64& acc) {
    term2(au.x, su.x, cu.x, av.x, sv.x, cv.x, acc);
    term2(au.y, su.y, cu.y, av.y, sv.y, cv.y, acc);
}

__device__ __forceinline__ float wgt(int u, int v, bool diag) {
    if (diag && u >= v) return 0.0f;
    return ((u < 32) == (v < 32)) ? 1.0f : -1.0f;
}

// Padded smem layout: row stride 36 floats (36 mod 32 = 4 -> conflict-free).
#define ROWSTR 36
#define ARRSTR 576            /* 16*36 */
#define BUFSTR 3456           /* 6*576 */
#define KSTAGE 32
#define NSTAGE 8              /* 256 k per block */

__global__ void __launch_bounds__(256, 2) pair_kernel() {
    __shared__ __align__(16) float smem[2 * BUFSTR];
    __shared__ double red[8];
    const int tid = threadIdx.x;
    const int pidx = blockIdx.y;
    const int I = c_PI[pidx], J = c_PJ[pidx];
    const int Ibase = I * 16, Jbase = J * 16;
    const int k0 = blockIdx.x * (KSTAGE * NSTAGE);
    const uint32_t sbase = (uint32_t)__cvta_generic_to_shared(smem);

    const float* srcs[6];
    srcs[0] = g_a + Ibase * D_LEN;
    srcs[1] = g_s + Ibase * D_LEN;
    srcs[2] = g_c + Ibase * D_LEN;
    srcs[3] = g_a + Jbase * D_LEN;
    srcs[4] = g_s + Jbase * D_LEN;
    srcs[5] = g_c + Jbase * D_LEN;

    // loader mapping: 768 float4 per stage = 3 per thread
    int larr[3], lgoff[3], lsoff[3];
    #pragma unroll
    for (int j = 0; j < 3; ++j) {
        int item = j * 256 + tid;
        int arr  = item >> 7;
        int rem  = item & 127;
        int row  = rem >> 3;
        int slot = rem & 7;
        larr[j]  = arr;
        lsoff[j] = arr * ARRSTR + row * ROWSTR + slot * 4;
        lgoff[j] = row * D_LEN + k0 + slot * 4;
    }

    #pragma unroll
    for (int j = 0; j < 3; ++j)
        cp16(sbase + 4 * lsoff[j], srcs[larr[j]] + lgoff[j]);
    asm volatile("cp.async.commit_group;\n");

    const int kq = tid >> 6;            // 0..3
    const int tu = (tid >> 3) & 7;      // 0..7
    const int tv = tid & 7;             // 0..7
    u64 acc00 = 0ULL, acc01 = 0ULL, acc10 = 0ULL, acc11 = 0ULL;

    const int ubase = tu * ROWSTR + kq * 8;
    const int vbase = 3 * ARRSTR + tv * ROWSTR + kq * 8;

    for (int st = 0; st < NSTAGE; ++st) {
        const int buf = st & 1;
        if (st + 1 < NSTAGE) {
            const int nb = buf ^ 1;
            #pragma unroll
            for (int j = 0; j < 3; ++j)
                cp16(sbase + 4 * (nb * BUFSTR + lsoff[j]),
                     srcs[larr[j]] + lgoff[j] + (st + 1) * KSTAGE);
            asm volatile("cp.async.commit_group;\n");
            asm volatile("cp.async.wait_group 1;\n");
        } else {
            asm volatile("cp.async.wait_group 0;\n");
        }
        __syncthreads();

        const float* ub = smem + buf * BUFSTR + ubase;
        const float* vb = smem + buf * BUFSTR + vbase;
        #pragma unroll
        for (int i = 0; i < 2; ++i) {
            const int o = i * 4;
            ulonglong2 au0 = *(const ulonglong2*)(ub + o);
            ulonglong2 su0 = *(const ulonglong2*)(ub + o + ARRSTR);
            ulonglong2 cu0 = *(const ulonglong2*)(ub + o + 2 * ARRSTR);
            ulonglong2 au1 = *(const ulonglong2*)(ub + o + 8 * ROWSTR);
            ulonglong2 su1 = *(const ulonglong2*)(ub + o + 8 * ROWSTR + ARRSTR);
            ulonglong2 cu1 = *(const ulonglong2*)(ub + o + 8 * ROWSTR + 2 * ARRSTR);
            ulonglong2 av0 = *(const ulonglong2*)(vb + o);
            ulonglong2 sv0 = *(const ulonglong2*)(vb + o + ARRSTR);
            ulonglong2 cv0 = *(const ulonglong2*)(vb + o + 2 * ARRSTR);
            ulonglong2 av1 = *(const ulonglong2*)(vb + o + 8 * ROWSTR);
            ulonglong2 sv1 = *(const ulonglong2*)(vb + o + 8 * ROWSTR + ARRSTR);
            ulonglong2 cv1 = *(const ulonglong2*)(vb + o + 8 * ROWSTR + 2 * ARRSTR);
            term4(au0, su0, cu0, av0, sv0, cv0, acc00);
            term4(au0, su0, cu0, av1, sv1, cv1, acc01);
            term4(au1, su1, cu1, av0, sv0, cv0, acc10);
            term4(au1, su1, cu1, av1, sv1, cv1, acc11);
        }
        __syncthreads();
    }

    const bool diag = (I == J);
    const int u0 = Ibase + tu, u1 = Ibase + tu + 8;
    const int v0 = Jbase + tv, v1 = Jbase + tv + 8;
    float tot = wgt(u0, v0, diag) * (f2lo(acc00) + f2hi(acc00))
              + wgt(u0, v1, diag) * (f2lo(acc01) + f2hi(acc01))
              + wgt(u1, v0, diag) * (f2lo(acc10) + f2hi(acc10))
              + wgt(u1, v1, diag) * (f2lo(acc11) + f2hi(acc11));

    double td = (double)tot;
    #pragma unroll
    for (int off = 16; off; off >>= 1)
        td += __shfl_down_sync(0xffffffffu, td, off);
    const int warp = tid >> 5, lane = tid & 31;
    if (lane == 0) red[warp] = td;
    __syncthreads();
    if (tid == 0) {
        double ss = 0.0;
        #pragma unroll
        for (int i = 0; i < 8; ++i) ss += red[i];
        g_part[blockIdx.y * 128 + blockIdx.x] = ss;
    }
}

// ---------------- final deterministic reduction ------------------------------
__global__ void final_kernel(float* __restrict__ out) {
    const int tid = threadIdx.x;
    double s = 0.0;
    for (int i = tid; i < 1280; i += 256) s += g_part[i];
    #pragma unroll
    for (int off = 16; off; off >>= 1)
        s += __shfl_down_sync(0xffffffffu, s, off);
    __shared__ double red[8];
    if ((tid & 31) == 0) red[tid >> 5] = s;
    __syncthreads();
    if (tid == 0) {
        double t = 0.0;
        #pragma unroll
        for (int i = 0; i < 8; ++i) t += red[i];
        out[0] = (float)(6.25 + t * (2.0 / 33554432.0));
    }
}

// ---------------- launch ------------------------------------------------------
extern "C" void kernel_launch(void* const* d_in, const int* in_sizes, int n_in,
                              void* d_out, int out_size) {
    (void)in_sizes; (void)n_in; (void)out_size;
    const float* A = (const float*)d_in[0];
    const float* B = (const float*)d_in[1];
    pool_kernel<<<2048, 256>>>(A, B);
    pair_kernel<<<dim3(128, 10), 256>>>();
    final_kernel<<<1, 256>>>((float*)d_out);
}

// round 5
// speedup vs baseline: 1.1170x; 1.1170x over previous
#include <cuda_runtime.h>
#include <cstdint>

#define D_LEN 32768

// ---------------- scratch (static device globals, no allocation) ------------
__device__ __align__(256) float g_a[64 * D_LEN];
__device__ __align__(256) float g_s[64 * D_LEN];
__device__ __align__(256) float g_c[64 * D_LEN];
__device__ double g_part[1280];

__constant__ int c_PI[10] = {0,0,0,0,1,1,1,2,2,3};
__constant__ int c_PJ[10] = {0,1,2,3,1,2,3,2,3,3};

// ---------------- fast fp32 sincos(x), |x| <~ 1000 --------------------------
__device__ __forceinline__ void sincos_fast(float x, float& s_out, float& c_out) {
    const float PIO2_A = 1.5707963705062866f;      // RN(pi/2)
    const float PIO2_B = -4.3711388286737929e-8f;  // pi/2 - PIO2_A
    float q = rintf(x * 0.63661977236758134f);     // 2/pi
    int qi = (int)q;
    float r = fmaf(q, -PIO2_A, x);
    r = fmaf(q, -PIO2_B, r);
    float z = r * r;
    float ps = fmaf(z, fmaf(z, -1.9515295891e-4f, 8.3321608736e-3f), -1.6666654611e-1f);
    float sinr = fmaf(r * z, ps, r);
    float pc = fmaf(z, fmaf(z, 2.443315711809948e-5f, -1.388731625493765e-3f),
                    4.166664568298827e-2f);
    float cosr = fmaf(z * z, pc, fmaf(z, -0.5f, 1.0f));
    float s, c;
    if (qi & 1) { s = cosr; c = -sinr; } else { s = sinr; c = cosr; }
    if (qi & 2) { s = -s; c = -c; }
    s_out = s; c_out = c;
}

// ---------------- pool(4) + sincos(100*m), 4 outputs/thread -----------------
__global__ void pool_kernel(const float* __restrict__ A, const float* __restrict__ B) {
    int idx = blockIdx.x * blockDim.x + threadIdx.x;   // [0, 524288)
    int tensor = idx >> 18;
    int rem = idx & 262143;
    int b  = rem >> 13;                                // 0..31
    int fg = rem & 8191;                               // feat group (4 feats)
    int c   = fg >> 6;
    int ph  = (fg >> 2) & 15;
    int pw0 = (fg & 3) * 4;
    const float* src = tensor ? B : A;
    const float* p = src + ((((b * 128 + c) * 64) + ph * 4) * 64 + pw0 * 4);

    float s0 = 0.f, s1 = 0.f, s2 = 0.f, s3 = 0.f;
    #pragma unroll
    for (int r = 0; r < 4; ++r) {
        const float* q = p + r * 64;
        float4 v0 = __ldcs((const float4*)(q));
        float4 v1 = __ldcs((const float4*)(q + 4));
        float4 v2 = __ldcs((const float4*)(q + 8));
        float4 v3 = __ldcs((const float4*)(q + 12));
        s0 += (v0.x + v0.y) + (v0.z + v0.w);
        s1 += (v1.x + v1.y) + (v1.z + v1.w);
        s2 += (v2.x + v2.y) + (v2.z + v2.w);
        s3 += (v3.x + v3.y) + (v3.z + v3.w);
    }
    float4 m = make_float4(s0 * 0.0625f, s1 * 0.0625f, s2 * 0.0625f, s3 * 0.0625f);
    float4 sv, cv;
    sincos_fast(100.0f * m.x, sv.x, cv.x);
    sincos_fast(100.0f * m.y, sv.y, cv.y);
    sincos_fast(100.0f * m.z, sv.z, cv.z);
    sincos_fast(100.0f * m.w, sv.w, cv.w);

    int row = tensor * 32 + b;
    int off = row * D_LEN + fg * 4;
    *(float4*)(g_a + off) = m;
    *(float4*)(g_s + off) = sv;
    *(float4*)(g_c + off) = cv;
}

// ---------------- pair kernel ------------------------------------------------
__device__ __forceinline__ void cp16(uint32_t dst, const float* src) {
    asm volatile("cp.async.cg.shared.global [%0], [%1], 16;\n" :: "r"(dst), "l"(src));
}
__device__ __forceinline__ float frcp(float x) {
    float r; asm("rcp.approx.ftz.f32 %0, %1;" : "=f"(r) : "f"(x)); return r;
}
__device__ __forceinline__ float wgt(int u, int v, bool diag) {
    if (diag && u >= v) return 0.0f;
    return ((u < 32) == (v < 32)) ? 1.0f : -1.0f;
}

// term = (su*cv - cu*sv) * rcp(d); exact d==0 collisions are skipped
// (their true contribution, T per event, is ~1e-6 relative -- negligible).
#define TERM1(AU,SU,CU,AV,SV,CV,ACC) do {                      \
    float d_ = (AU) - (AV);                                    \
    float r_ = frcp(d_);                                       \
    float t_ = (CU) * (SV);                                    \
    float n_ = fmaf((SU), (CV), -t_);                          \
    if (d_ != 0.0f) (ACC) = fmaf(n_, r_, (ACC));               \
} while (0)

#define TERM4(AU,SU,CU,AV,SV,CV,ACC) do {                      \
    TERM1((AU).x,(SU).x,(CU).x,(AV).x,(SV).x,(CV).x,(ACC));    \
    TERM1((AU).y,(SU).y,(CU).y,(AV).y,(SV).y,(CV).y,(ACC));    \
    TERM1((AU).z,(SU).z,(CU).z,(AV).z,(SV).z,(CV).z,(ACC));    \
    TERM1((AU).w,(SU).w,(CU).w,(AV).w,(SV).w,(CV).w,(ACC));    \
} while (0)

// Padded smem layout: 64 data floats/row + 8 pad => ROWSTR 72 (72 mod 32 = 8).
// Per LDS.128: 8 distinct bank-quads x 4-way broadcast -> conflict-free.
#define ROWSTR 72
#define ARRSTR 1152           /* 16*72 */
#define BUFSTR 6912           /* 6*1152 floats; 27648 B per buffer */
#define KSTAGE 64
#define NSTAGE 4              /* 256 k per block */

__global__ void __launch_bounds__(256, 2) pair_kernel() {
    __shared__ __align__(16) float smem[2 * BUFSTR];
    __shared__ double red[8];
    const int tid = threadIdx.x;
    const int pidx = blockIdx.y;
    const int I = c_PI[pidx], J = c_PJ[pidx];
    const int Ibase = I * 16, Jbase = J * 16;
    const int k0 = blockIdx.x * (KSTAGE * NSTAGE);
    const uint32_t sbase = (uint32_t)__cvta_generic_to_shared(smem);

    const float* srcs[6];
    srcs[0] = g_a + Ibase * D_LEN;
    srcs[1] = g_s + Ibase * D_LEN;
    srcs[2] = g_c + Ibase * D_LEN;
    srcs[3] = g_a + Jbase * D_LEN;
    srcs[4] = g_s + Jbase * D_LEN;
    srcs[5] = g_c + Jbase * D_LEN;

    // loader mapping: 1536 float4 per stage = 6 per thread (one per array)
    const int lrow  = tid >> 4;          // 0..15
    const int lslot = tid & 15;          // 0..15
    const int lsoff = lrow * ROWSTR + lslot * 4;          // + j*ARRSTR
    const int lgoff = lrow * D_LEN + k0 + lslot * 4;      // + srcs[j]

    #pragma unroll
    for (int j = 0; j < 6; ++j)
        cp16(sbase + 4 * (j * ARRSTR + lsoff), srcs[j] + lgoff);
    asm volatile("cp.async.commit_group;\n");

    // compute mapping: kq 16-way k split, 4x4 register tile over rows
    const int kq = tid >> 4;             // 0..15 -> float4 slot
    const int tu = (tid >> 2) & 3;       // 0..3
    const int tv = tid & 3;              // 0..3
    float acc[4][4];
    #pragma unroll
    for (int i = 0; i < 4; ++i)
        #pragma unroll
        for (int j = 0; j < 4; ++j) acc[i][j] = 0.0f;

    for (int st = 0; st < NSTAGE; ++st) {
        const int buf = st & 1;
        if (st + 1 < NSTAGE) {
            const int nb = buf ^ 1;
            #pragma unroll
            for (int j = 0; j < 6; ++j)
                cp16(sbase + 4 * (nb * BUFSTR + j * ARRSTR + lsoff),
                     srcs[j] + lgoff + (st + 1) * KSTAGE);
            asm volatile("cp.async.commit_group;\n");
            asm volatile("cp.async.wait_group 1;\n");
        } else {
            asm volatile("cp.async.wait_group 0;\n");
        }
        __syncthreads();

        const float* base = smem + buf * BUFSTR + kq * 4;

        float4 av[4], sv[4], cv[4];
        #pragma unroll
        for (int j = 0; j < 4; ++j) {
            const int vo = (tv + 4 * j) * ROWSTR;
            av[j] = *(const float4*)(base + 3 * ARRSTR + vo);
            sv[j] = *(const float4*)(base + 4 * ARRSTR + vo);
            cv[j] = *(const float4*)(base + 5 * ARRSTR + vo);
        }
        #pragma unroll
        for (int i = 0; i < 4; ++i) {
            const int uo = (tu + 4 * i) * ROWSTR;
            float4 au = *(const float4*)(base + uo);
            float4 su = *(const float4*)(base + ARRSTR + uo);
            float4 cu = *(const float4*)(base + 2 * ARRSTR + uo);
            #pragma unroll
            for (int j = 0; j < 4; ++j)
                TERM4(au, su, cu, av[j], sv[j], cv[j], acc[i][j]);
        }
        __syncthreads();
    }

    // weights (diagonal tile-pairs count only u<v; cross-tensor sign -1)
    const bool diag = (I == J);
    float tot = 0.0f;
    #pragma unroll
    for (int i = 0; i < 4; ++i) {
        const int u = Ibase + tu + 4 * i;
        #pragma unroll
        for (int j = 0; j < 4; ++j) {
            const int v = Jbase + tv + 4 * j;
            tot += wgt(u, v, diag) * acc[i][j];
        }
    }

    // deterministic block reduction in double
    double td = (double)tot;
    #pragma unroll
    for (int off = 16; off; off >>= 1)
        td += __shfl_down_sync(0xffffffffu, td, off);
    const int warp = tid >> 5, lane = tid & 31;
    if (lane == 0) red[warp] = td;
    __syncthreads();
    if (tid == 0) {
        double ss = 0.0;
        #pragma unroll
        for (int i = 0; i < 8; ++i) ss += red[i];
        g_part[blockIdx.y * 128 + blockIdx.x] = ss;
    }
}

// ---------------- final deterministic reduction ------------------------------
__global__ void final_kernel(float* __restrict__ out) {
    const int tid = threadIdx.x;
    double s = 0.0;
    for (int i = tid; i < 1280; i += 256) s += g_part[i];
    #pragma unroll
    for (int off = 16; off; off >>= 1)
        s += __shfl_down_sync(0xffffffffu, s, off);
    __shared__ double red[8];
    if ((tid & 31) == 0) red[tid >> 5] = s;
    __syncthreads();
    if (tid == 0) {
        double t = 0.0;
        #pragma unroll
        for (int i = 0; i < 8; ++i) t += red[i];
        out[0] = (float)(6.25 + t * (2.0 / 33554432.0));
    }
}

// ---------------- launch ------------------------------------------------------
extern "C" void kernel_launch(void* const* d_in, const int* in_sizes, int n_in,
                              void* d_out, int out_size) {
    (void)in_sizes; (void)n_in; (void)out_size;
    const float* A = (const float*)d_in[0];
    const float* B = (const float*)d_in[1];
    pool_kernel<<<2048, 256>>>(A, B);
    pair_kernel<<<dim3(128, 10), 256>>>();
    final_kernel<<<1, 256>>>((float*)d_out);
}